// round 11
// baseline (speedup 1.0000x reference)
#include <cuda_runtime.h>
#include <cuda_bf16.h>

// Problem constants (fixed by setup_inputs)
#define B_CHAIN 16384
#define S_SIDE  15
#define NATM    (1 + B_CHAIN + B_CHAIN * S_SIDE)   // 262145
#define NOUT    (NATM - 1)                         // 262144
#define NBLK    128                                // scan blocks
#define CHUNK   (B_CHAIN / NBLK)                   // 128 gen0 atoms per scan block
#define AP_BLKS 512                                // apply blocks (32 chains each)
#define AP_CHN  32                                 // chains per apply block
#define INV_BLKS (NOUT / 128)                      // 2048 inverse-perm blocks

// Scratch (no cudaMalloc allowed)
__device__ float4 g_scan4[B_CHAIN * 3];  // gen0 chunk-local inclusive scans (3 rows/atom)
__device__ float  g_btot[NBLK * 12];     // per-chunk totals
__device__ float4 g_pref4[NBLK * 3];     // exclusive chunk prefixes
__device__ int    g_inv[NOUT];           // inverse permutation of kin_id[1:]
__device__ float4 g_tmp4[NATM];          // coords by atom index

// ---- accurate polynomial sincos: |x| < ~20, ~1 ulp (cephes kernels) ----
__device__ __forceinline__ void psincos(float x, float* s, float* c) {
    const float INV_PIO2 = 0.6366197723675814f;
    const float PIO2_HI  = 1.57079637050628662109375f;   // 0x3FC90FDB
    const float PIO2_LO  = -4.371138828673793e-8f;
    int q   = __float2int_rn(x * INV_PIO2);
    float k = (float)q;
    float r = fmaf(-k, PIO2_HI, x);
    r       = fmaf(-k, PIO2_LO, r);
    float r2 = r * r;
    float sp = fmaf(r2, -1.9515296e-4f, 8.3321609e-3f);
    sp       = fmaf(r2, sp, -1.66666546e-1f);
    float sr = fmaf(r * r2, sp, r);
    float cp = fmaf(r2, 2.44331571e-5f, -1.38873163e-3f);
    cp       = fmaf(r2, cp, 4.16666457e-2f);
    float cr = fmaf(r2 * r2, cp, fmaf(r2, -0.5f, 1.0f));
    bool swap = q & 1;
    float ss = swap ? cr : sr;
    float cc = swap ? sr : cr;
    *s = (q & 2)       ? -ss : ss;
    *c = ((q + 1) & 2) ? -cc : cc;
}

// C = A @ B for 3x4 rigid transforms, row-major [r00 r01 r02 tx | r1x | r2x]
__device__ __forceinline__ void compose(const float* __restrict__ A,
                                        const float* __restrict__ B,
                                        float* __restrict__ C) {
#pragma unroll
    for (int r = 0; r < 3; r++) {
        float a0 = A[r*4+0], a1 = A[r*4+1], a2 = A[r*4+2], a3 = A[r*4+3];
        C[r*4+0] = a0*B[0] + a1*B[4] + a2*B[8];
        C[r*4+1] = a0*B[1] + a1*B[5] + a2*B[9];
        C[r*4+2] = a0*B[2] + a1*B[6] + a2*B[10];
        C[r*4+3] = a0*B[3] + a1*B[7] + a2*B[11] + a3;
    }
}

__device__ __forceinline__ void mat_copy(float* __restrict__ d, const float* __restrict__ s) {
#pragma unroll
    for (int k = 0; k < 12; k++) d[k] = s[k];
}

__device__ __forceinline__ void mat_ident(float* __restrict__ d) {
    d[0]=1.f; d[1]=0.f; d[2]=0.f; d[3]=0.f;
    d[4]=0.f; d[5]=1.f; d[6]=0.f; d[7]=0.f;
    d[8]=0.f; d[9]=0.f; d[10]=1.f; d[11]=0.f;
}

// Bond transform: Rx(d0) Rz(d1) T(d2,0,0) Rx(d3), closed form, poly trig.
__device__ __forceinline__ void bond_ht(float d0, float d1, float d2, float d3,
                                        float* __restrict__ M) {
    float sa, ca, sb, cb, sd, cd;
    psincos(d0, &sa, &ca);
    psincos(d1, &sb, &cb);
    psincos(d3, &sd, &cd);
    M[0] = cb;     M[1] = -sb*cd;            M[2]  = sb*sd;             M[3]  = d2*cb;
    M[4] = ca*sb;  M[5] = ca*cb*cd - sa*sd;  M[6]  = -ca*cb*sd - sa*cd; M[7]  = ca*d2*sb;
    M[8] = sa*sb;  M[9] = sa*cb*cd + ca*sd;  M[10] = -sa*cb*sd + ca*cd; M[11] = sa*d2*sb;
}

// Atom 1 jump (d4=d5=0): T(d0,d1,d2) @ Rx(d3)
__device__ __forceinline__ void jump_ht(float d0, float d1, float d2, float d3,
                                        float* __restrict__ M) {
    float sd, cd; psincos(d3, &sd, &cd);
    M[0] = 1.f; M[1] = 0.f; M[2] = 0.f;  M[3]  = d0;
    M[4] = 0.f; M[5] = cd;  M[6] = -sd;  M[7]  = d1;
    M[8] = 0.f; M[9] = sd;  M[10] = cd;  M[11] = d2;
}

__device__ __forceinline__ void shfl_up_mat(float* __restrict__ P,
                                            const float* __restrict__ M,
                                            int off, int width) {
#pragma unroll
    for (int k = 0; k < 12; k++)
        P[k] = __shfl_up_sync(0xffffffffu, M[k], off, width);
}

// Warp inclusive scan (order-preserving, width 32)
__device__ __forceinline__ void warp_scan(float* __restrict__ M, int lane) {
#pragma unroll
    for (int off = 1; off < 32; off <<= 1) {
        float P[12], C[12];
        shfl_up_mat(P, M, off, 32);
        compose(P, M, C);
        if (lane >= off) mat_copy(M, C);
    }
}

// ---------------- K1: gen0 chunk inclusive scans + totals ----------------
__global__ void __launch_bounds__(CHUNK) k_scan(const float* __restrict__ dofs) {
    __shared__ float s_w[4 * 12];
    const int tid  = threadIdx.x;
    const int lane = tid & 31;
    const int wid  = tid >> 5;
    const int gi   = blockIdx.x * CHUNK + tid;     // atom gi+1

    float M[12];
    {
        const float4 d = __ldg((const float4*)(dofs + 4 * gi));
        if (gi == 0) jump_ht(d.x, d.y, d.z, d.w, M);
        else         bond_ht(d.x, d.y, d.z, d.w, M);
    }

    warp_scan(M, lane);
    if (lane == 31) mat_copy(&s_w[wid * 12], M);
    __syncthreads();

    float W[12]; mat_ident(W);
    for (int i = 0; i < wid; i++) {
        float C[12]; compose(W, &s_w[i * 12], C); mat_copy(W, C);
    }
    float F[12];
    compose(W, M, F);

#pragma unroll
    for (int r = 0; r < 3; r++)
        g_scan4[gi * 3 + r] = make_float4(F[4*r], F[4*r+1], F[4*r+2], F[4*r+3]);
    if (tid == CHUNK - 1) mat_copy(&g_btot[blockIdx.x * 12], F);
}

// ---------------- K2: exclusive prefixes of the 128 chunk totals ----------------
__global__ void __launch_bounds__(NBLK) k_pref() {
    __shared__ float s_w[4 * 12];
    const int tid  = threadIdx.x;
    const int lane = tid & 31;
    const int wid  = tid >> 5;

    float M[12];
    mat_copy(M, &g_btot[tid * 12]);
    warp_scan(M, lane);
    if (lane == 31) mat_copy(&s_w[wid * 12], M);
    __syncthreads();

    float W[12]; mat_ident(W);
    for (int i = 0; i < wid; i++) {
        float C[12]; compose(W, &s_w[i * 12], C); mat_copy(W, C);
    }
    float F[12];
    compose(W, M, F);             // inclusive over btot[0..tid]

    if (tid == 0) {
        g_pref4[0] = make_float4(1.f, 0.f, 0.f, 0.f);
        g_pref4[1] = make_float4(0.f, 1.f, 0.f, 0.f);
        g_pref4[2] = make_float4(0.f, 0.f, 1.f, 0.f);
    }
    if (tid < NBLK - 1) {
#pragma unroll
        for (int r = 0; r < 3; r++)
            g_pref4[(tid + 1) * 3 + r] = make_float4(F[4*r], F[4*r+1], F[4*r+2], F[4*r+3]);
    }
}

// ---------------- K3: apply (blocks < AP_BLKS) + inverse perm (rest) ----------------
__global__ void __launch_bounds__(128) k_apply(const float* __restrict__ dofs,
                                               const int* __restrict__ kin_id) {
    if (blockIdx.x >= AP_BLKS) {
        // inverse permutation: g_inv[kin_id[a]] = a
        const int i = (blockIdx.x - AP_BLKS) * 128 + threadIdx.x;   // 0..NOUT-1
        const int a = i + 1;
        g_inv[__ldg(&kin_id[a])] = a;
        return;
    }

    __shared__ float4 s_out[AP_CHN * 16];          // 8 KB staging (512 atoms)

    const int b   = blockIdx.x;
    const int tid = threadIdx.x;
    const int l   = tid >> 2;                      // local chain 0..31
    const int j   = tid & 3;                       // lane within chain
    const int c   = b * AP_CHN + l;                // global chain 0..16383
    const int sbase = B_CHAIN + c * S_SIDE;        // dof row of side atom 0
    const int first = (j == 0) ? 0 : 3 + (j - 1) * 4;
    const int nA    = (j == 0) ? 3 : 4;

    // Local side matrices (poly trig)
    float Lm[4][12];
#pragma unroll
    for (int i = 0; i < 4; i++) {
        if (i < nA) {
            const float4 d = __ldg((const float4*)(dofs + 4 * (sbase + first + i)));
            bond_ht(d.x, d.y, d.z, d.w, Lm[i]);
        }
    }

    // Segment product S. Lane 0 = gen0 global, emits while walking.
    float S[12];
    if (j == 0) {
        float P[12], Sc[12];
        const int ch = c >> 7;                     // chunk index (CHUNK=128)
#pragma unroll
        for (int r = 0; r < 3; r++) {
            const float4 pv = g_pref4[ch * 3 + r];
            P[4*r] = pv.x; P[4*r+1] = pv.y; P[4*r+2] = pv.z; P[4*r+3] = pv.w;
            const float4 sv = g_scan4[c * 3 + r];
            Sc[4*r] = sv.x; Sc[4*r+1] = sv.y; Sc[4*r+2] = sv.z; Sc[4*r+3] = sv.w;
        }
        compose(P, Sc, S);                         // gen0 global transform
        s_out[l * 16 + 0] = make_float4(S[3], S[7], S[11], 0.f);
#pragma unroll
        for (int i = 0; i < 3; i++) {
            float C[12]; compose(S, Lm[i], C); mat_copy(S, C);
            s_out[l * 16 + 1 + i] = make_float4(S[3], S[7], S[11], 0.f);
        }
    } else {
        mat_copy(S, Lm[0]);
#pragma unroll
        for (int i = 1; i < 4; i++) {
            float C[12]; compose(S, Lm[i], C); mat_copy(S, C);
        }
    }

    // width-4 inclusive scan (2 steps)
#pragma unroll
    for (int off = 1; off < 4; off <<= 1) {
        float Q[12], C[12];
        shfl_up_mat(Q, S, off, 4);
        compose(Q, S, C);
        if (j >= off) mat_copy(S, C);
    }

    float X[12];
    shfl_up_mat(X, S, 1, 4);        // start for lane j = inclusive of lane j-1

    if (j > 0) {
        float cur[12];
        mat_copy(cur, X);
#pragma unroll
        for (int i = 0; i < 4; i++) {
            float C[12]; compose(cur, Lm[i], C); mat_copy(cur, C);
            s_out[l * 16 + 1 + first + i] = make_float4(cur[3], cur[7], cur[11], 0.f);
        }
    }
    __syncthreads();

    // Coalesced copy to g_tmp4. s_out slot l*16+0 = gen0 atom of chain l,
    // slots l*16+1+s = side atom s of chain l.
    const int g0_base   = b * AP_CHN + 1;                   // gen0 atoms (32)
    const int side_base = 1 + B_CHAIN + b * AP_CHN * S_SIDE; // side atoms (480)
#pragma unroll
    for (int t = tid; t < AP_CHN * 16; t += 128) {
        const int lc = t >> 4;        // chain
        const int s  = t & 15;        // 0 = gen0, 1..15 = side s-1
        const float4 v = s_out[t];
        if (s == 0) g_tmp4[g0_base + lc] = v;
        else        g_tmp4[side_base + lc * S_SIDE + (s - 1)] = v;
    }
}

// ---------------- K4: out[o] = g_tmp4[g_inv[o]].xyz ----------------
__global__ void __launch_bounds__(256) k_gather(float* __restrict__ out) {
    const int o = blockIdx.x * 256 + threadIdx.x;   // 0..NOUT-1
    const int a = __ldg(&g_inv[o]);
    const float4 v = g_tmp4[a];
    out[3*o + 0] = v.x;
    out[3*o + 1] = v.y;
    out[3*o + 2] = v.z;
}

extern "C" void kernel_launch(void* const* d_in, const int* in_sizes, int n_in,
                              void* d_out, int out_size) {
    const float* dofs   = (const float*)d_in[0];   // (NATM-1)*4
    const int*   kin_id = (const int*)  d_in[8];   // NATM
    float*       out    = (float*)d_out;           // (NATM-1)*3

    k_scan<<<NBLK, CHUNK>>>(dofs);
    k_pref<<<1, NBLK>>>();
    k_apply<<<AP_BLKS + INV_BLKS, 128>>>(dofs, kin_id);
    k_gather<<<NOUT / 256, 256>>>(out);
}

// round 15
// speedup vs baseline: 1.1100x; 1.1100x over previous
#include <cuda_runtime.h>
#include <cuda_bf16.h>

// Problem constants (fixed by setup_inputs)
#define B_CHAIN 16384
#define S_SIDE  15
#define NATM    (1 + B_CHAIN + B_CHAIN * S_SIDE)   // 262145
#define NOUT    (NATM - 1)                         // 262144
#define NBLK    128                                // scan blocks
#define CHUNK   (B_CHAIN / NBLK)                   // 128 gen0 atoms per scan block
#define AP_BLKS 512                                // apply blocks (32 chains each)
#define AP_CHN  32                                 // chains per apply block

// Scratch (no cudaMalloc allowed)
__device__ float4 g_scan4[B_CHAIN * 3];  // gen0 chunk-local inclusive scans (3 rows/atom)
__device__ float  g_btot[NBLK * 12];     // per-chunk totals
__device__ float4 g_pref4[NBLK * 3];     // exclusive chunk prefixes

// ---- accurate polynomial sincos: |x| < ~20, ~1 ulp (cephes kernels) ----
__device__ __forceinline__ void psincos(float x, float* s, float* c) {
    const float INV_PIO2 = 0.6366197723675814f;
    const float PIO2_HI  = 1.57079637050628662109375f;
    const float PIO2_LO  = -4.371138828673793e-8f;
    int q   = __float2int_rn(x * INV_PIO2);
    float k = (float)q;
    float r = fmaf(-k, PIO2_HI, x);
    r       = fmaf(-k, PIO2_LO, r);
    float r2 = r * r;
    float sp = fmaf(r2, -1.9515296e-4f, 8.3321609e-3f);
    sp       = fmaf(r2, sp, -1.66666546e-1f);
    float sr = fmaf(r * r2, sp, r);
    float cp = fmaf(r2, 2.44331571e-5f, -1.38873163e-3f);
    cp       = fmaf(r2, cp, 4.16666457e-2f);
    float cr = fmaf(r2 * r2, cp, fmaf(r2, -0.5f, 1.0f));
    bool swap = q & 1;
    float ss = swap ? cr : sr;
    float cc = swap ? sr : cr;
    *s = (q & 2)       ? -ss : ss;
    *c = ((q + 1) & 2) ? -cc : cc;
}

// C = A @ B for 3x4 rigid transforms, row-major [r00 r01 r02 tx | r1x | r2x]
__device__ __forceinline__ void compose(const float* __restrict__ A,
                                        const float* __restrict__ B,
                                        float* __restrict__ C) {
#pragma unroll
    for (int r = 0; r < 3; r++) {
        float a0 = A[r*4+0], a1 = A[r*4+1], a2 = A[r*4+2], a3 = A[r*4+3];
        C[r*4+0] = a0*B[0] + a1*B[4] + a2*B[8];
        C[r*4+1] = a0*B[1] + a1*B[5] + a2*B[9];
        C[r*4+2] = a0*B[2] + a1*B[6] + a2*B[10];
        C[r*4+3] = a0*B[3] + a1*B[7] + a2*B[11] + a3;
    }
}

__device__ __forceinline__ void mat_copy(float* __restrict__ d, const float* __restrict__ s) {
#pragma unroll
    for (int k = 0; k < 12; k++) d[k] = s[k];
}

__device__ __forceinline__ void mat_ident(float* __restrict__ d) {
    d[0]=1.f; d[1]=0.f; d[2]=0.f; d[3]=0.f;
    d[4]=0.f; d[5]=1.f; d[6]=0.f; d[7]=0.f;
    d[8]=0.f; d[9]=0.f; d[10]=1.f; d[11]=0.f;
}

// Bond transform: Rx(d0) Rz(d1) T(d2,0,0) Rx(d3), closed form, poly trig.
__device__ __forceinline__ void bond_ht(float d0, float d1, float d2, float d3,
                                        float* __restrict__ M) {
    float sa, ca, sb, cb, sd, cd;
    psincos(d0, &sa, &ca);
    psincos(d1, &sb, &cb);
    psincos(d3, &sd, &cd);
    M[0] = cb;     M[1] = -sb*cd;            M[2]  = sb*sd;             M[3]  = d2*cb;
    M[4] = ca*sb;  M[5] = ca*cb*cd - sa*sd;  M[6]  = -ca*cb*sd - sa*cd; M[7]  = ca*d2*sb;
    M[8] = sa*sb;  M[9] = sa*cb*cd + ca*sd;  M[10] = -sa*cb*sd + ca*cd; M[11] = sa*d2*sb;
}

// Atom 1 jump (d4=d5=0): T(d0,d1,d2) @ Rx(d3)
__device__ __forceinline__ void jump_ht(float d0, float d1, float d2, float d3,
                                        float* __restrict__ M) {
    float sd, cd; psincos(d3, &sd, &cd);
    M[0] = 1.f; M[1] = 0.f; M[2] = 0.f;  M[3]  = d0;
    M[4] = 0.f; M[5] = cd;  M[6] = -sd;  M[7]  = d1;
    M[8] = 0.f; M[9] = sd;  M[10] = cd;  M[11] = d2;
}

__device__ __forceinline__ void shfl_up_mat(float* __restrict__ P,
                                            const float* __restrict__ M,
                                            int off, int width) {
#pragma unroll
    for (int k = 0; k < 12; k++)
        P[k] = __shfl_up_sync(0xffffffffu, M[k], off, width);
}

// Warp inclusive scan (order-preserving, width 32)
__device__ __forceinline__ void warp_scan(float* __restrict__ M, int lane) {
#pragma unroll
    for (int off = 1; off < 32; off <<= 1) {
        float P[12], C[12];
        shfl_up_mat(P, M, off, 32);
        compose(P, M, C);
        if (lane >= off) mat_copy(M, C);
    }
}

// ---------------- K1: gen0 chunk inclusive scans + totals ----------------
__global__ void __launch_bounds__(CHUNK) k_scan(const float* __restrict__ dofs) {
    __shared__ float s_w[4 * 12];
    const int tid  = threadIdx.x;
    const int lane = tid & 31;
    const int wid  = tid >> 5;
    const int gi   = blockIdx.x * CHUNK + tid;     // atom gi+1

    float M[12];
    {
        const float4 d = __ldg((const float4*)(dofs + 4 * gi));
        if (gi == 0) jump_ht(d.x, d.y, d.z, d.w, M);
        else         bond_ht(d.x, d.y, d.z, d.w, M);
    }

    warp_scan(M, lane);
    if (lane == 31) mat_copy(&s_w[wid * 12], M);
    __syncthreads();

    float W[12]; mat_ident(W);
    for (int i = 0; i < wid; i++) {
        float C[12]; compose(W, &s_w[i * 12], C); mat_copy(W, C);
    }
    float F[12];
    compose(W, M, F);

#pragma unroll
    for (int r = 0; r < 3; r++)
        g_scan4[gi * 3 + r] = make_float4(F[4*r], F[4*r+1], F[4*r+2], F[4*r+3]);
    if (tid == CHUNK - 1) mat_copy(&g_btot[blockIdx.x * 12], F);
}

// ---------------- K2: exclusive prefixes of the 128 chunk totals ----------------
__global__ void __launch_bounds__(NBLK) k_pref() {
    __shared__ float s_w[4 * 12];
    const int tid  = threadIdx.x;
    const int lane = tid & 31;
    const int wid  = tid >> 5;

    float M[12];
    mat_copy(M, &g_btot[tid * 12]);
    warp_scan(M, lane);
    if (lane == 31) mat_copy(&s_w[wid * 12], M);
    __syncthreads();

    float W[12]; mat_ident(W);
    for (int i = 0; i < wid; i++) {
        float C[12]; compose(W, &s_w[i * 12], C); mat_copy(W, C);
    }
    float F[12];
    compose(W, M, F);             // inclusive over btot[0..tid]

    if (tid == 0) {
        g_pref4[0] = make_float4(1.f, 0.f, 0.f, 0.f);
        g_pref4[1] = make_float4(0.f, 1.f, 0.f, 0.f);
        g_pref4[2] = make_float4(0.f, 0.f, 1.f, 0.f);
    }
    if (tid < NBLK - 1) {
#pragma unroll
        for (int r = 0; r < 3; r++)
            g_pref4[(tid + 1) * 3 + r] = make_float4(F[4*r], F[4*r+1], F[4*r+2], F[4*r+3]);
    }
}

// ---------------- K3: apply + DIRECT scatter to out ----------------
// 512 blocks x 128 threads; 4 lanes per chain, 4 atoms serial per lane.
// Stores are fire-and-forget: scatter wavefronts drain under the FMA work.
__global__ void __launch_bounds__(128) k_apply(const float* __restrict__ dofs,
                                               const int* __restrict__ kin_id,
                                               float* __restrict__ out) {
    const int b   = blockIdx.x;
    const int tid = threadIdx.x;
    const int l   = tid >> 2;                      // local chain 0..31
    const int j   = tid & 3;                       // lane within chain
    const int c   = b * AP_CHN + l;                // global chain 0..16383
    const int sbase = B_CHAIN + c * S_SIDE;        // dof row of side atom 0
    const int first = (j == 0) ? 0 : 3 + (j - 1) * 4;
    const int nA    = (j == 0) ? 3 : 4;

    // Local side matrices (poly trig)
    float Lm[4][12];
#pragma unroll
    for (int i = 0; i < 4; i++) {
        if (i < nA) {
            const float4 d = __ldg((const float4*)(dofs + 4 * (sbase + first + i)));
            bond_ht(d.x, d.y, d.z, d.w, Lm[i]);
        }
    }

    // kin ids for this lane's atoms
    int kid[4];
#pragma unroll
    for (int i = 0; i < 4; i++)
        if (i < nA) kid[i] = __ldg(&kin_id[1 + sbase + first + i]);

    // Segment product S. Lane 0 = gen0 global, emits while walking.
    float S[12];
    if (j == 0) {
        float P[12], Sc[12];
        const int ch = c >> 7;                     // chunk index (CHUNK=128)
#pragma unroll
        for (int r = 0; r < 3; r++) {
            const float4 pv = __ldg(&g_pref4[ch * 3 + r]);
            P[4*r] = pv.x; P[4*r+1] = pv.y; P[4*r+2] = pv.z; P[4*r+3] = pv.w;
            const float4 sv = __ldg(&g_scan4[c * 3 + r]);
            Sc[4*r] = sv.x; Sc[4*r+1] = sv.y; Sc[4*r+2] = sv.z; Sc[4*r+3] = sv.w;
        }
        compose(P, Sc, S);                         // gen0 global transform
        const int pk = __ldg(&kin_id[c + 1]);
        out[3*pk + 0] = S[3]; out[3*pk + 1] = S[7]; out[3*pk + 2] = S[11];
#pragma unroll
        for (int i = 0; i < 3; i++) {
            float C[12]; compose(S, Lm[i], C); mat_copy(S, C);
            out[3*kid[i] + 0] = S[3];
            out[3*kid[i] + 1] = S[7];
            out[3*kid[i] + 2] = S[11];
        }
    } else {
        mat_copy(S, Lm[0]);
#pragma unroll
        for (int i = 1; i < 4; i++) {
            float C[12]; compose(S, Lm[i], C); mat_copy(S, C);
        }
    }

    // width-4 inclusive scan (2 steps)
#pragma unroll
    for (int off = 1; off < 4; off <<= 1) {
        float Q[12], C[12];
        shfl_up_mat(Q, S, off, 4);
        compose(Q, S, C);
        if (j >= off) mat_copy(S, C);
    }

    float X[12];
    shfl_up_mat(X, S, 1, 4);        // start for lane j = inclusive of lane j-1

    if (j > 0) {
        float cur[12];
        mat_copy(cur, X);
#pragma unroll
        for (int i = 0; i < 4; i++) {
            float C[12]; compose(cur, Lm[i], C); mat_copy(cur, C);
            out[3*kid[i] + 0] = cur[3];
            out[3*kid[i] + 1] = cur[7];
            out[3*kid[i] + 2] = cur[11];
        }
    }
}

extern "C" void kernel_launch(void* const* d_in, const int* in_sizes, int n_in,
                              void* d_out, int out_size) {
    const float* dofs   = (const float*)d_in[0];   // (NATM-1)*4
    const int*   kin_id = (const int*)  d_in[8];   // NATM
    float*       out    = (float*)d_out;           // (NATM-1)*3

    k_scan<<<NBLK, CHUNK>>>(dofs);
    k_pref<<<1, NBLK>>>();
    k_apply<<<AP_BLKS, 128>>>(dofs, kin_id, out);
}